// round 4
// baseline (speedup 1.0000x reference)
#include <cuda_runtime.h>
#include <cuda_bf16.h>

// ---------------- problem constants ----------------
#define NN 100000
#define EE 3200000
#define GG 128
#define DIN 128
#define DH  256
#define DOUT 64
#define BN_EPS 1e-3f

// ---------------- device scratch (static, no allocs) ----------------
__device__ int   g_deg_in [NN];
__device__ int   g_deg_out[NN];
__device__ float g_norm_src[NN];
__device__ float g_norm_dst[NN];
__device__ int   g_off[NN + 1];
__device__ int   g_cursor[NN];
__device__ int   g_csr_src[EE];
__device__ float g_agg[(size_t)NN * DH];
__device__ float g_h1 [(size_t)NN * DH];
__device__ float g_h2 [(size_t)NN * DH];
__device__ float g_W0f[DIN * DH];
__device__ float g_Wf [2 * DH * DH];
__device__ float g_bf [3 * DH];
__device__ float g_pool[GG * DH];
__device__ int   g_gcount[GG];

// ---------------- kernels ----------------

__global__ void k_zero() {
    int i = blockIdx.x * 256 + threadIdx.x;
    if (i < NN) { g_deg_in[i] = 0; g_deg_out[i] = 0; }
    if (i < GG * DH) g_pool[i] = 0.f;
    if (i < GG) g_gcount[i] = 0;
}

__global__ void k_deg(const int* __restrict__ src, const int* __restrict__ dst) {
    int e = blockIdx.x * 256 + threadIdx.x;
    if (e < EE) {
        atomicAdd(&g_deg_out[src[e]], 1);
        atomicAdd(&g_deg_in [dst[e]], 1);
    }
}

__global__ void k_norm() {
    int i = blockIdx.x * 256 + threadIdx.x;
    if (i < NN) {
        g_norm_src[i] = rsqrtf(fmaxf((float)g_deg_out[i], 1.f));
        g_norm_dst[i] = rsqrtf(fmaxf((float)g_deg_in [i], 1.f));
    }
}

// single-block exclusive scan of g_deg_in -> g_off (and g_cursor copy)
__global__ void k_scan() {
    __shared__ int partial[1024];
    const int tid = threadIdx.x;
    const int chunk = (NN + 1023) / 1024;
    int start = tid * chunk;
    int end = start + chunk; if (end > NN) end = NN;
    if (start > NN) start = NN;
    int s = 0;
    for (int i = start; i < end; i++) s += g_deg_in[i];
    partial[tid] = s;
    __syncthreads();
    for (int d = 1; d < 1024; d <<= 1) {
        int v = (tid >= d) ? partial[tid - d] : 0;
        __syncthreads();
        partial[tid] += v;
        __syncthreads();
    }
    int running = (tid == 0) ? 0 : partial[tid - 1];
    for (int i = start; i < end; i++) {
        g_off[i] = running;
        g_cursor[i] = running;
        running += g_deg_in[i];
    }
    if (tid == 0) g_off[NN] = EE;
}

__global__ void k_csr(const int* __restrict__ src, const int* __restrict__ dst) {
    int e = blockIdx.x * 256 + threadIdx.x;
    if (e < EE) {
        int pos = atomicAdd(&g_cursor[dst[e]], 1);
        g_csr_src[pos] = src[e];
    }
}

// fold BN scale into weights and biases
__global__ void k_fold(const float* __restrict__ W0, const float* __restrict__ b0,
                       const float* __restrict__ W,  const float* __restrict__ b,
                       const float* __restrict__ gamma, const float* __restrict__ beta,
                       const float* __restrict__ mean,  const float* __restrict__ var) {
    int idx = blockIdx.x * 256 + threadIdx.x;
    if (idx < 2 * DH * DH) {
        int l = idx >> 16;           // 0,1 -> layers 1,2
        int j = idx & (DH - 1);
        float a = gamma[(l + 1) * DH + j] * rsqrtf(var[(l + 1) * DH + j] + BN_EPS);
        g_Wf[idx] = W[idx] * a;
    }
    if (idx < DIN * DH) {
        int j = idx & (DH - 1);
        float a = gamma[j] * rsqrtf(var[j] + BN_EPS);
        g_W0f[idx] = W0[idx] * a;
    }
    if (idx < 3 * DH) {
        int l = idx >> 8;
        int j = idx & (DH - 1);
        float a = gamma[idx] * rsqrtf(var[idx] + BN_EPS);
        float bl = (l == 0) ? b0[j] : b[(l - 1) * DH + j];
        g_bf[idx] = bl * a + beta[idx] - mean[idx] * a;
    }
}

// gather-only SpMM: agg[n,:] = sum_{e in CSR(n)} x[src_e,:] * norm_src[src_e]
template <int D>
__global__ void __launch_bounds__(D) k_agg(const float* __restrict__ x,
                                           float* __restrict__ agg) {
    __shared__ int   sh_s[64];
    __shared__ float sh_ns[64];
    const int n = blockIdx.x;
    const int f = threadIdx.x;
    const int beg = g_off[n], end = g_off[n + 1];
    float acc = 0.f;
    for (int base = beg; base < end; base += 64) {
        int m = end - base; if (m > 64) m = 64;
        if (f < m) {
            int s = g_csr_src[base + f];
            sh_s[f]  = s;
            sh_ns[f] = g_norm_src[s];
        }
        __syncthreads();
        for (int j = 0; j < m; j++)
            acc = fmaf(__ldg(x + (size_t)sh_s[j] * D + f), sh_ns[j], acc);
        __syncthreads();
    }
    agg[(size_t)n * D + f] = acc;
}

// SGEMM C[N x 256] = A[N x K] @ B[K x 256], fused epilogue:
// v = acc * norm_dst[row] + biasf[col]; v = relu(v); v += res[row,col] (optional)
__global__ void __launch_bounds__(256) k_gemm(const float* __restrict__ A, int K,
                                              const float* __restrict__ B,
                                              const float* __restrict__ biasf,
                                              const float* __restrict__ res,
                                              float* __restrict__ C) {
    __shared__ float As[8][128];
    __shared__ float Bs[8][128];
    const int tid = threadIdx.x;
    const int tr = tid >> 4;          // 0..15
    const int tc = tid & 15;          // 0..15
    const int rowBase = blockIdx.y * 128;
    const int colBase = blockIdx.x * 128;

    const int aRow = tid >> 1;        // 0..127
    const int aKv  = (tid & 1) * 4;   // 0 or 4
    const int bK   = tid >> 5;        // 0..7
    const int bC   = (tid & 31) * 4;  // 0..124

    float acc[8][8];
#pragma unroll
    for (int i = 0; i < 8; i++)
#pragma unroll
        for (int j = 0; j < 8; j++) acc[i][j] = 0.f;

    int ar = rowBase + aRow; if (ar > NN - 1) ar = NN - 1;

    for (int k0 = 0; k0 < K; k0 += 8) {
        float4 av = *(const float4*)(A + (size_t)ar * K + k0 + aKv);
        As[aKv + 0][aRow] = av.x;
        As[aKv + 1][aRow] = av.y;
        As[aKv + 2][aRow] = av.z;
        As[aKv + 3][aRow] = av.w;
        *(float4*)(&Bs[bK][bC]) = *(const float4*)(B + (size_t)(k0 + bK) * DH + colBase + bC);
        __syncthreads();
#pragma unroll
        for (int kk = 0; kk < 8; kk++) {
            float ra[8], rb[8];
            *(float4*)(ra)     = *(const float4*)(&As[kk][tr * 8]);
            *(float4*)(ra + 4) = *(const float4*)(&As[kk][tr * 8 + 4]);
            *(float4*)(rb)     = *(const float4*)(&Bs[kk][tc * 8]);
            *(float4*)(rb + 4) = *(const float4*)(&Bs[kk][tc * 8 + 4]);
#pragma unroll
            for (int i = 0; i < 8; i++)
#pragma unroll
                for (int j = 0; j < 8; j++)
                    acc[i][j] = fmaf(ra[i], rb[j], acc[i][j]);
        }
        __syncthreads();
    }

#pragma unroll
    for (int i = 0; i < 8; i++) {
        int r = rowBase + tr * 8 + i;
        if (r < NN) {
            float nd = g_norm_dst[r];
#pragma unroll
            for (int j = 0; j < 8; j += 4) {
                int c = colBase + tc * 8 + j;
                float4 v;
                v.x = fmaxf(fmaf(acc[i][j + 0], nd, biasf[c + 0]), 0.f);
                v.y = fmaxf(fmaf(acc[i][j + 1], nd, biasf[c + 1]), 0.f);
                v.z = fmaxf(fmaf(acc[i][j + 2], nd, biasf[c + 2]), 0.f);
                v.w = fmaxf(fmaf(acc[i][j + 3], nd, biasf[c + 3]), 0.f);
                if (res) {
                    float4 rv = *(const float4*)(res + (size_t)r * DH + c);
                    v.x += rv.x; v.y += rv.y; v.z += rv.z; v.w += rv.w;
                }
                *(float4*)(C + (size_t)r * DH + c) = v;
            }
        }
    }
}

// per-graph mean-pool accumulation (graph_ids sorted)
__global__ void __launch_bounds__(256) k_pool(const float* __restrict__ h,
                                              const int* __restrict__ gid) {
    const int f = threadIdx.x;
    int n0 = blockIdx.x * 64;
    int n1 = n0 + 64; if (n1 > NN) n1 = NN;
    if (n0 >= NN) return;
    float acc = 0.f;
    int cnt = 0;
    int cur = gid[n0];
    for (int n = n0; n < n1; n++) {
        int g = gid[n];
        if (g != cur) {
            atomicAdd(&g_pool[cur * DH + f], acc);
            if (f == 0) atomicAdd(&g_gcount[cur], cnt);
            acc = 0.f; cnt = 0; cur = g;
        }
        acc += h[(size_t)n * DH + f];
        cnt++;
    }
    atomicAdd(&g_pool[cur * DH + f], acc);
    if (f == 0) atomicAdd(&g_gcount[cur], cnt);
}

// head: out[g,:] = (pool[g]/count[g]) @ Wp + bp
__global__ void __launch_bounds__(64) k_head(const float* __restrict__ Wp,
                                             const float* __restrict__ bp,
                                             float* __restrict__ out) {
    const int g = blockIdx.x;
    const int j = threadIdx.x;
    __shared__ float sp[DH];
    float inv = 1.f / fmaxf((float)g_gcount[g], 1.f);
    for (int k = j; k < DH; k += 64) sp[k] = g_pool[g * DH + k] * inv;
    __syncthreads();
    float s = 0.f;
    for (int k = 0; k < DH; k++)
        s = fmaf(sp[k], Wp[k * DOUT + j], s);
    out[g * DOUT + j] = s + bp[j];
}

// ---------------- launch ----------------
extern "C" void kernel_launch(void* const* d_in, const int* in_sizes, int n_in,
                              void* d_out, int out_size) {
    const float* h    = (const float*)d_in[0];
    const float* W0   = (const float*)d_in[1];
    const float* b0   = (const float*)d_in[2];
    const float* W    = (const float*)d_in[3];
    const float* b    = (const float*)d_in[4];
    const float* bng  = (const float*)d_in[5];
    const float* bnb  = (const float*)d_in[6];
    const float* bnm  = (const float*)d_in[7];
    const float* bnv  = (const float*)d_in[8];
    const float* Wp   = (const float*)d_in[9];
    const float* bp   = (const float*)d_in[10];
    const int*   src  = (const int*)d_in[11];
    const int*   dst  = (const int*)d_in[12];
    const int*   gid  = (const int*)d_in[13];
    float* out = (float*)d_out;

    float *agg, *h1, *h2, *W0f, *Wf, *bf;
    cudaGetSymbolAddress((void**)&agg, g_agg);
    cudaGetSymbolAddress((void**)&h1,  g_h1);
    cudaGetSymbolAddress((void**)&h2,  g_h2);
    cudaGetSymbolAddress((void**)&W0f, g_W0f);
    cudaGetSymbolAddress((void**)&Wf,  g_Wf);
    cudaGetSymbolAddress((void**)&bf,  g_bf);

    const int nb_n = (NN + 255) / 256;
    const int nb_e = (EE + 255) / 256;

    k_zero<<<nb_n, 256>>>();
    k_deg<<<nb_e, 256>>>(src, dst);
    k_norm<<<nb_n, 256>>>();
    k_scan<<<1, 1024>>>();
    k_csr<<<nb_e, 256>>>(src, dst);
    k_fold<<<(2 * DH * DH + 255) / 256, 256>>>(W0, b0, W, b, bng, bnb, bnm, bnv);

    dim3 gemmGrid(DH / 128, (NN + 127) / 128);

    // layer 0: agg in D=128 over input h, GEMM K=128, no residual
    k_agg<DIN><<<NN, DIN>>>(h, agg);
    k_gemm<<<gemmGrid, 256>>>(agg, DIN, W0f, bf, nullptr, h1);

    // layer 1: agg over h1 (D=256), GEMM K=256, residual h1
    k_agg<DH><<<NN, DH>>>(h1, agg);
    k_gemm<<<gemmGrid, 256>>>(agg, DH, Wf, bf + DH, h1, h2);

    // layer 2: agg over h2, residual h2, write back into h1
    k_agg<DH><<<NN, DH>>>(h2, agg);
    k_gemm<<<gemmGrid, 256>>>(agg, DH, Wf + DH * DH, bf + 2 * DH, h2, h1);

    // pooling + head
    k_pool<<<(NN + 63) / 64, 256>>>(h1, gid);
    k_head<<<GG, DOUT>>>(Wp, bp, out);
}

// round 7
// speedup vs baseline: 1.9945x; 1.9945x over previous
#include <cuda_runtime.h>
#include <cuda_bf16.h>
#include <cstdint>

// ---------------- problem constants ----------------
#define NN 100000
#define EE 3200000
#define GG 128
#define DIN 128
#define DH  256
#define DOUT 64
#define BN_EPS 1e-3f
#define NB_SCAN ((NN + 1023) / 1024)   // 98

// ---------------- device scratch (static, no allocs) ----------------
__device__ int   g_deg_in [NN];
__device__ int   g_deg_out[NN];
__device__ float g_norm_src[NN];
__device__ float g_norm_dst[NN];
__device__ int   g_off[NN + 1];
__device__ int   g_cursor[NN];
__device__ int   g_bsum[NB_SCAN];
__device__ int   g_csr_src[EE];
__device__ float g_agg[(size_t)NN * DH];
__device__ float g_h1 [(size_t)NN * DH];
__device__ float g_h2 [(size_t)NN * DH];
__device__ float g_W0f[DIN * DH];
__device__ float g_Wf [2 * DH * DH];
__device__ float g_bf [3 * DH];
__device__ float g_pool[GG * DH];
__device__ int   g_gcount[GG];

// ---------------- helpers ----------------
__device__ __forceinline__ uint32_t f2tf(float f) {
    uint32_t u;
    asm("cvt.rna.tf32.f32 %0, %1;" : "=r"(u) : "f"(f));
    return u;
}

// ---------------- preprocessing kernels ----------------

__global__ void k_zero() {
    int i = blockIdx.x * 256 + threadIdx.x;
    if (i < NN) { g_deg_in[i] = 0; g_deg_out[i] = 0; }
    if (i < GG * DH) g_pool[i] = 0.f;
    if (i < GG) g_gcount[i] = 0;
}

__global__ void k_deg(const int* __restrict__ src, const int* __restrict__ dst) {
    int e = blockIdx.x * 256 + threadIdx.x;
    if (e < EE) {
        atomicAdd(&g_deg_out[src[e]], 1);
        atomicAdd(&g_deg_in [dst[e]], 1);
    }
}

__global__ void k_norm() {
    int i = blockIdx.x * 256 + threadIdx.x;
    if (i < NN) {
        g_norm_src[i] = rsqrtf(fmaxf((float)g_deg_out[i], 1.f));
        g_norm_dst[i] = rsqrtf(fmaxf((float)g_deg_in [i], 1.f));
    }
}

// multi-block exclusive scan of g_deg_in -> g_off
// stage A: per-block inclusive scan; write (incl - v) and block totals
__global__ void __launch_bounds__(1024) k_scanA() {
    __shared__ int sh[1024];
    const int t = threadIdx.x;
    const int i = blockIdx.x * 1024 + t;
    int v = (i < NN) ? g_deg_in[i] : 0;
    sh[t] = v;
    __syncthreads();
#pragma unroll
    for (int d = 1; d < 1024; d <<= 1) {
        int u = (t >= d) ? sh[t - d] : 0;
        __syncthreads();
        sh[t] += u;
        __syncthreads();
    }
    if (i < NN) g_off[i] = sh[t] - v;
    if (t == 1023) g_bsum[blockIdx.x] = sh[t];
}

// stage B: serial exclusive scan of 98 block sums (tiny)
__global__ void k_scanB() {
    int run = 0;
    for (int b = 0; b < NB_SCAN; b++) {
        int v = g_bsum[b];
        g_bsum[b] = run;
        run += v;
    }
}

// stage C: add block offsets, mirror into cursor, close the array
__global__ void __launch_bounds__(1024) k_scanC() {
    const int i = blockIdx.x * 1024 + threadIdx.x;
    if (i < NN) {
        int o = g_off[i] + g_bsum[blockIdx.x];
        g_off[i] = o;
        g_cursor[i] = o;
    }
    if (i == 0) g_off[NN] = EE;
}

__global__ void k_csr(const int* __restrict__ src, const int* __restrict__ dst) {
    int e = blockIdx.x * 256 + threadIdx.x;
    if (e < EE) {
        int pos = atomicAdd(&g_cursor[dst[e]], 1);
        g_csr_src[pos] = src[e];
    }
}

// fold BN scale into weights and biases
__global__ void k_fold(const float* __restrict__ W0, const float* __restrict__ b0,
                       const float* __restrict__ W,  const float* __restrict__ b,
                       const float* __restrict__ gamma, const float* __restrict__ beta,
                       const float* __restrict__ mean,  const float* __restrict__ var) {
    int idx = blockIdx.x * 256 + threadIdx.x;
    if (idx < 2 * DH * DH) {
        int l = idx >> 16;
        int j = idx & (DH - 1);
        float a = gamma[(l + 1) * DH + j] * rsqrtf(var[(l + 1) * DH + j] + BN_EPS);
        g_Wf[idx] = W[idx] * a;
    }
    if (idx < DIN * DH) {
        int j = idx & (DH - 1);
        float a = gamma[j] * rsqrtf(var[j] + BN_EPS);
        g_W0f[idx] = W0[idx] * a;
    }
    if (idx < 3 * DH) {
        int l = idx >> 8;
        int j = idx & (DH - 1);
        float a = gamma[idx] * rsqrtf(var[idx] + BN_EPS);
        float bl = (l == 0) ? b0[j] : b[(l - 1) * DH + j];
        g_bf[idx] = bl * a + beta[idx] - mean[idx] * a;
    }
}

// ---------------- aggregation (gather SpMM, float4) ----------------
// agg[n,:] = sum_{e in CSR(n)} x[src_e,:] * norm_src[src_e]
template <int D>
__global__ void __launch_bounds__(256) k_agg(const float* __restrict__ x,
                                             float* __restrict__ agg) {
    constexpr int V = D / 4;      // float4 lanes per row (32 or 64)
    constexpr int G = 256 / V;    // edge groups per block (8 or 4)
    __shared__ int   sh_s[64];
    __shared__ float sh_ns[64];
    __shared__ float4 red[256];
    const int n = blockIdx.x;
    const int tid = threadIdx.x;
    const int g = tid / V;
    const int v = tid % V;
    const int beg = g_off[n], end = g_off[n + 1];

    float4 acc = make_float4(0.f, 0.f, 0.f, 0.f);
    for (int base = beg; base < end; base += 64) {
        int m = end - base; if (m > 64) m = 64;
        if (tid < m) {
            int s = g_csr_src[base + tid];
            sh_s[tid]  = s;
            sh_ns[tid] = g_norm_src[s];
        }
        __syncthreads();
        for (int j = g; j < m; j += G) {
            const float4 xv = *(const float4*)(x + (size_t)sh_s[j] * D + v * 4);
            const float w = sh_ns[j];
            acc.x = fmaf(xv.x, w, acc.x);
            acc.y = fmaf(xv.y, w, acc.y);
            acc.z = fmaf(xv.z, w, acc.z);
            acc.w = fmaf(xv.w, w, acc.w);
        }
        __syncthreads();
    }

    red[tid] = acc;
    __syncthreads();
#pragma unroll
    for (int half = G / 2; half > 0; half >>= 1) {
        if (g < half) {
            float4 o = red[(g + half) * V + v];
            acc.x += o.x; acc.y += o.y; acc.z += o.z; acc.w += o.w;
            red[tid] = acc;
        }
        __syncthreads();
    }
    if (g == 0)
        *(float4*)(agg + (size_t)n * D + v * 4) = acc;
}

// ---------------- TF32 tensor-core GEMM ----------------
// C[N x 256] = A[N x K] @ B[K x 256], epilogue:
// v = relu(acc * norm_dst[row] + biasf[col]); v += res[row,col] (optional)
#define AST 132
__global__ void __launch_bounds__(256) k_gemm_tf32(const float* __restrict__ A, int K,
                                                   const float* __restrict__ B,
                                                   const float* __restrict__ biasf,
                                                   const float* __restrict__ res,
                                                   float* __restrict__ C) {
    __shared__ uint32_t As[16 * AST];
    __shared__ uint32_t Bs[16 * AST];
    const int tid  = threadIdx.x;
    const int lane = tid & 31;
    const int warp = tid >> 5;
    const int wm = warp & 3;      // 4 warps along M (32 rows each)
    const int wn = warp >> 2;     // 2 warps along N (64 cols each)
    const int gq  = lane >> 2;    // 0..7
    const int tig = lane & 3;     // 0..3
    const int rowBase = blockIdx.y * 128;
    const int colBase = blockIdx.x * 128;

    // A staging mapping: slot tid -> (row=tid>>2, kq=tid&3); slot tid+256 -> row+64
    const int r0 = tid >> 2;
    const int kq = tid & 3;
    int ar0 = rowBase + r0;       if (ar0 > NN - 1) ar0 = NN - 1;
    int ar1 = rowBase + r0 + 64;  if (ar1 > NN - 1) ar1 = NN - 1;
    // B staging mapping: slot tid -> (kr=tid>>5, n4=(tid&31)*4); slot tid+256 -> kr+8
    const int kr = tid >> 5;
    const int n4 = (tid & 31) * 4;

    float acc[2][8][4];
#pragma unroll
    for (int mt = 0; mt < 2; mt++)
#pragma unroll
        for (int nt = 0; nt < 8; nt++)
#pragma unroll
            for (int q = 0; q < 4; q++) acc[mt][nt][q] = 0.f;

    for (int k0 = 0; k0 < K; k0 += 16) {
        // stage A (transpose to k-major, convert to tf32)
        float4 av0 = *(const float4*)(A + (size_t)ar0 * K + k0 + kq * 4);
        float4 av1 = *(const float4*)(A + (size_t)ar1 * K + k0 + kq * 4);
        As[(kq * 4 + 0) * AST + r0] = f2tf(av0.x);
        As[(kq * 4 + 1) * AST + r0] = f2tf(av0.y);
        As[(kq * 4 + 2) * AST + r0] = f2tf(av0.z);
        As[(kq * 4 + 3) * AST + r0] = f2tf(av0.w);
        As[(kq * 4 + 0) * AST + r0 + 64] = f2tf(av1.x);
        As[(kq * 4 + 1) * AST + r0 + 64] = f2tf(av1.y);
        As[(kq * 4 + 2) * AST + r0 + 64] = f2tf(av1.z);
        As[(kq * 4 + 3) * AST + r0 + 64] = f2tf(av1.w);
        // stage B (already k-major)
        float4 bv0 = *(const float4*)(B + (size_t)(k0 + kr)     * DH + colBase + n4);
        float4 bv1 = *(const float4*)(B + (size_t)(k0 + kr + 8) * DH + colBase + n4);
        uint4 bu0 = make_uint4(f2tf(bv0.x), f2tf(bv0.y), f2tf(bv0.z), f2tf(bv0.w));
        uint4 bu1 = make_uint4(f2tf(bv1.x), f2tf(bv1.y), f2tf(bv1.z), f2tf(bv1.w));
        *(uint4*)(&Bs[kr       * AST + n4]) = bu0;
        *(uint4*)(&Bs[(kr + 8) * AST + n4]) = bu1;
        __syncthreads();

#pragma unroll
        for (int kk = 0; kk < 16; kk += 8) {
            uint32_t af[2][4];
#pragma unroll
            for (int mt = 0; mt < 2; mt++) {
                int mb = wm * 32 + mt * 16 + gq;
                af[mt][0] = As[(kk + tig)     * AST + mb];
                af[mt][1] = As[(kk + tig)     * AST + mb + 8];
                af[mt][2] = As[(kk + tig + 4) * AST + mb];
                af[mt][3] = As[(kk + tig + 4) * AST + mb + 8];
            }
#pragma unroll
            for (int nt = 0; nt < 8; nt++) {
                int nb = wn * 64 + nt * 8 + gq;
                uint32_t b0 = Bs[(kk + tig)     * AST + nb];
                uint32_t b1 = Bs[(kk + tig + 4) * AST + nb];
#pragma unroll
                for (int mt = 0; mt < 2; mt++) {
                    asm volatile(
                        "mma.sync.aligned.m16n8k8.row.col.f32.tf32.tf32.f32 "
                        "{%0,%1,%2,%3}, {%4,%5,%6,%7}, {%8,%9}, {%0,%1,%2,%3};\n"
                        : "+f"(acc[mt][nt][0]), "+f"(acc[mt][nt][1]),
                          "+f"(acc[mt][nt][2]), "+f"(acc[mt][nt][3])
                        : "r"(af[mt][0]), "r"(af[mt][1]), "r"(af[mt][2]), "r"(af[mt][3]),
                          "r"(b0), "r"(b1));
                }
            }
        }
        __syncthreads();
    }

    // epilogue
#pragma unroll
    for (int mt = 0; mt < 2; mt++) {
#pragma unroll
        for (int half = 0; half < 2; half++) {
            int r = rowBase + wm * 32 + mt * 16 + gq + half * 8;
            if (r < NN) {
                float nd = g_norm_dst[r];
#pragma unroll
                for (int nt = 0; nt < 8; nt++) {
                    int c = colBase + wn * 64 + nt * 8 + 2 * tig;
                    float v0 = fmaxf(fmaf(acc[mt][nt][half * 2 + 0], nd, biasf[c]),     0.f);
                    float v1 = fmaxf(fmaf(acc[mt][nt][half * 2 + 1], nd, biasf[c + 1]), 0.f);
                    if (res) {
                        float2 rv = *(const float2*)(res + (size_t)r * DH + c);
                        v0 += rv.x; v1 += rv.y;
                    }
                    float2 o; o.x = v0; o.y = v1;
                    *(float2*)(C + (size_t)r * DH + c) = o;
                }
            }
        }
    }
}

// ---------------- pooling + head ----------------

__global__ void __launch_bounds__(256) k_pool(const float* __restrict__ h,
                                              const int* __restrict__ gid) {
    const int f = threadIdx.x;
    int n0 = blockIdx.x * 64;
    int n1 = n0 + 64; if (n1 > NN) n1 = NN;
    if (n0 >= NN) return;
    float acc = 0.f;
    int cnt = 0;
    int cur = gid[n0];
    for (int n = n0; n < n1; n++) {
        int g = gid[n];
        if (g != cur) {
            atomicAdd(&g_pool[cur * DH + f], acc);
            if (f == 0) atomicAdd(&g_gcount[cur], cnt);
            acc = 0.f; cnt = 0; cur = g;
        }
        acc += h[(size_t)n * DH + f];
        cnt++;
    }
    atomicAdd(&g_pool[cur * DH + f], acc);
    if (f == 0) atomicAdd(&g_gcount[cur], cnt);
}

__global__ void __launch_bounds__(64) k_head(const float* __restrict__ Wp,
                                             const float* __restrict__ bp,
                                             float* __restrict__ out) {
    const int g = blockIdx.x;
    const int j = threadIdx.x;
    __shared__ float sp[DH];
    float inv = 1.f / fmaxf((float)g_gcount[g], 1.f);
    for (int k = j; k < DH; k += 64) sp[k] = g_pool[g * DH + k] * inv;
    __syncthreads();
    float s = 0.f;
    for (int k = 0; k < DH; k++)
        s = fmaf(sp[k], Wp[k * DOUT + j], s);
    out[g * DOUT + j] = s + bp[j];
}

// ---------------- launch ----------------
extern "C" void kernel_launch(void* const* d_in, const int* in_sizes, int n_in,
                              void* d_out, int out_size) {
    const float* h    = (const float*)d_in[0];
    const float* W0   = (const float*)d_in[1];
    const float* b0   = (const float*)d_in[2];
    const float* W    = (const float*)d_in[3];
    const float* b    = (const float*)d_in[4];
    const float* bng  = (const float*)d_in[5];
    const float* bnb  = (const float*)d_in[6];
    const float* bnm  = (const float*)d_in[7];
    const float* bnv  = (const float*)d_in[8];
    const float* Wp   = (const float*)d_in[9];
    const float* bp   = (const float*)d_in[10];
    const int*   src  = (const int*)d_in[11];
    const int*   dst  = (const int*)d_in[12];
    const int*   gid  = (const int*)d_in[13];
    float* out = (float*)d_out;

    float *agg, *h1, *h2, *W0f, *Wf, *bf;
    cudaGetSymbolAddress((void**)&agg, g_agg);
    cudaGetSymbolAddress((void**)&h1,  g_h1);
    cudaGetSymbolAddress((void**)&h2,  g_h2);
    cudaGetSymbolAddress((void**)&W0f, g_W0f);
    cudaGetSymbolAddress((void**)&Wf,  g_Wf);
    cudaGetSymbolAddress((void**)&bf,  g_bf);

    const int nb_n = (NN + 255) / 256;
    const int nb_e = (EE + 255) / 256;

    k_zero<<<nb_n, 256>>>();
    k_deg<<<nb_e, 256>>>(src, dst);
    k_norm<<<nb_n, 256>>>();
    k_scanA<<<NB_SCAN, 1024>>>();
    k_scanB<<<1, 1>>>();
    k_scanC<<<NB_SCAN, 1024>>>();
    k_csr<<<nb_e, 256>>>(src, dst);
    k_fold<<<(2 * DH * DH + 255) / 256, 256>>>(W0, b0, W, b, bng, bnb, bnm, bnv);

    dim3 gemmGrid(DH / 128, (NN + 127) / 128);

    // layer 0: agg in D=128 over input h, GEMM K=128, no residual
    k_agg<DIN><<<NN, 256>>>(h, agg);
    k_gemm_tf32<<<gemmGrid, 256>>>(agg, DIN, W0f, bf, nullptr, h1);

    // layer 1: agg over h1 (D=256), GEMM K=256, residual h1
    k_agg<DH><<<NN, 256>>>(h1, agg);
    k_gemm_tf32<<<gemmGrid, 256>>>(agg, DH, Wf, bf + DH, h1, h2);

    // layer 2: agg over h2, residual h2, write into h1
    k_agg<DH><<<NN, 256>>>(h2, agg);
    k_gemm_tf32<<<gemmGrid, 256>>>(agg, DH, Wf + DH * DH, bf + 2 * DH, h2, h1);

    // pooling + head
    k_pool<<<(NN + 63) / 64, 256>>>(h1, gid);
    k_head<<<GG, DOUT>>>(Wp, bp, out);
}